// round 6
// baseline (speedup 1.0000x reference)
#include <cuda_runtime.h>
#include <math_constants.h>

// MiniRocket round 5 (resubmit — previous bench was an infra failure):
// round-4 direct-compare design with the vhi<vlo guard bug fixed
// (lim clamped to 0 when a segment lies wholly in the pad zone).
//   Per feature, per position-pair: FSET.BF (mask) x2 + one IADD3.
// One exact wave: 592 blocks = 148 SMs x 4 blocks.

#define NCH    8
#define LEN    1024
#define NKER   84
#define HALO   32
#define PITCHX 528
#define PITCHS 464
#define TOTF   9996

// partial counts [i][n][j][32]; mr_fin re-zeros after reading (graph-safe).
__device__ int g_partial[4 * 64 * NKER * 32];

__device__ __forceinline__ int fset_gt(float a, float b)
{
    int m;   // 0xFFFFFFFF if a > b else 0
    asm("set.gt.s32.f32 %0, %1, %2;" : "=r"(m) : "f"(a), "f"(b));
    return m;
}

// ---------------------------------------------------------------------------
__global__ __launch_bounds__(128, 4)
void mr_main(const float* __restrict__ x,
             const float* __restrict__ biases,
             const int* __restrict__ ci)
{
    __shared__ __align__(16) float Xq[NCH * PITCHX];
    __shared__ __align__(16) float Sq[NCH * PITCHS];
    __shared__ float bsh[NKER * 30];
    __shared__ int comb[NKER];

    const int tid = threadIdx.x, warp = tid >> 5, lane = tid & 31;

    // block -> (dilation, local block, range): 160+144*3 = 592 = 148*4.
    // d=1 path is scalar-load (more instrs) so it gets smaller ranges.
    int bid = blockIdx.x;
    int i, bl, range;
    if (bid < 160) { i = 0; bl = bid; range = 410; }
    else { int r = bid - 160; i = 1 + r / 144; bl = r % 144; range = 456; }
    const int d = 1 << i, p = 4 * d;
    const int nf = (i == 3) ? 29 : 30;

    if (tid < NKER) {                      // 84 lexicographic triples of 0..8
        int t = 0, val = 0;
        for (int a = 0; a < 9; a++)
            for (int b2 = a + 1; b2 < 9; b2++)
                for (int c2 = b2 + 1; c2 < 9; c2++) {
                    if (t == tid) val = a | (b2 << 8) | (c2 << 16);
                    t++;
                }
        comb[tid] = val;
    }
    for (int k = tid; k < NKER * nf; k += 128)
        bsh[k] = biases[i * 2520 + k];

    const int g0 = bl * range;
    const int g1 = min(g0 + range, 65536);
    int g = g0;
    while (g < g1) {                       // <= 2 sample-segments per block
        const int n = g >> 10;
        const int ls = g & 1023;
        const int seglen = min(LEN - ls, g1 - g);

        __syncthreads();
        for (int c = 0; c < NCH; c++) {    // stage padded segment of x[n]
            const float* xc = x + (n * NCH + c) * LEN;
            for (int u = tid; u < seglen + 2 * HALO; u += 128) {
                int l = ls - HALO + u;
                Xq[c * PITCHX + u] = (l >= 0 && l < LEN) ? xc[l] : 0.0f;
            }
        }
        __syncthreads();
        for (int c = 0; c < NCH; c++) {    // per-channel 9-tap dilated sums
            const float* xb = Xq + c * PITCHX + HALO;
            float* sc = Sq + c * PITCHS;
            for (int u = tid; u < seglen; u += 128) {
                float s = ((xb[u-4*d] + xb[u-3*d]) + (xb[u-2*d] + xb[u-d]))
                        + ((xb[u] + xb[u+d]) + (xb[u+2*d] + xb[u+3*d])) + xb[u+4*d];
                sc[u] = s;
            }
        }
        __syncthreads();

        for (int jj = 0; jj < 21; jj++) {  // each warp owns 21 kernels
            const int j = warp * 21 + jj;
            const int cm = comb[j];
            const int da = (((cm      ) & 255) - 4) * d;
            const int db = (((cm >>  8) & 255) - 4) * d;
            const int dc = (((cm >> 16) & 255) - 4) * d;
            const int* cp = ci + (i * NKER + j) * 3;
            const int c0 = cp[0], c1 = cp[1], c2 = cp[2];
            const float* X0 = Xq + c0 * PITCHX + HALO;
            const float* X1 = Xq + c1 * PITCHX + HALO;
            const float* X2 = Xq + c2 * PITCHX + HALO;
            const float* S0 = Sq + c0 * PITCHS;
            const float* S1 = Sq + c1 * PITCHS;
            const float* S2 = Sq + c2 * PITCHS;

            int vlo = 0, vhi = seglen;
            if ((i + j) & 1) {             // odd parity: interior [p, L-p)
                vlo = max(0, p - ls);
                vhi = min(seglen, LEN - p - ls);
            }
            // CLAMPED: segment may lie wholly in the pad zone (vhi < vlo);
            // unsigned wrap here was the round-4 correctness bug.
            const unsigned lim = (unsigned)max(0, vhi - vlo);

            float bv[30];
            int   cnt[30];
            const float* bp = bsh + j * nf;
            #pragma unroll
            for (int f = 0; f < 30; f++) {
                bv[f]  = (f < nf) ? bp[f] : CUDART_INF_F;  // inf: never counted
                cnt[f] = 0;
            }

            if (i == 0) {                  // d=1: odd tap offsets -> scalar
                for (int u0 = lane; u0 < seglen; u0 += 64) {
                    const int u1 = u0 + 32;
                    float ax = ((X0[u0+da] + X0[u0+db]) + (X0[u0+dc] + X1[u0+da]))
                             + ((X1[u0+db] + X1[u0+dc]) + (X2[u0+da] + X2[u0+db]))
                             + X2[u0+dc];
                    float cx = fmaf(3.0f, ax, -(S0[u0] + S1[u0] + S2[u0]));
                    float ay = ((X0[u1+da] + X0[u1+db]) + (X0[u1+dc] + X1[u1+da]))
                             + ((X1[u1+db] + X1[u1+dc]) + (X2[u1+da] + X2[u1+db]))
                             + X2[u1+dc];
                    float cy = fmaf(3.0f, ay, -(S0[u1] + S1[u1] + S2[u1]));
                    if ((unsigned)(u0 - vlo) >= lim) cx = -CUDART_INF_F;
                    if ((unsigned)(u1 - vlo) >= lim) cy = -CUDART_INF_F;
                    #pragma unroll
                    for (int f = 0; f < 30; f++) {
                        int m0 = fset_gt(cx, bv[f]);
                        int m1 = fset_gt(cy, bv[f]);
                        cnt[f] += m0 + m1;               // one IADD3
                    }
                }
            } else {                       // even d: float2, aligned
                for (int u0 = 2 * lane; u0 < seglen; u0 += 64) {
                    float2 a0 = *(const float2*)(X0 + u0 + da);
                    float2 a1 = *(const float2*)(X0 + u0 + db);
                    float2 a2 = *(const float2*)(X0 + u0 + dc);
                    float2 a3 = *(const float2*)(X1 + u0 + da);
                    float2 a4 = *(const float2*)(X1 + u0 + db);
                    float2 a5 = *(const float2*)(X1 + u0 + dc);
                    float2 a6 = *(const float2*)(X2 + u0 + da);
                    float2 a7 = *(const float2*)(X2 + u0 + db);
                    float2 a8 = *(const float2*)(X2 + u0 + dc);
                    float2 s0 = *(const float2*)(S0 + u0);
                    float2 s1 = *(const float2*)(S1 + u0);
                    float2 s2 = *(const float2*)(S2 + u0);
                    float ax = ((a0.x+a1.x)+(a2.x+a3.x)) + ((a4.x+a5.x)+(a6.x+a7.x)) + a8.x;
                    float ay = ((a0.y+a1.y)+(a2.y+a3.y)) + ((a4.y+a5.y)+(a6.y+a7.y)) + a8.y;
                    float cx = fmaf(3.0f, ax, -(s0.x + s1.x + s2.x));
                    float cy = fmaf(3.0f, ay, -(s0.y + s1.y + s2.y));
                    const unsigned q0 = (unsigned)(u0 - vlo);
                    if (q0 >= lim)      cx = -CUDART_INF_F;
                    if (q0 + 1u >= lim) cy = -CUDART_INF_F;  // u1 = u0+1
                    #pragma unroll
                    for (int f = 0; f < 30; f++) {
                        int m0 = fset_gt(cx, bv[f]);
                        int m1 = fset_gt(cy, bv[f]);
                        cnt[f] += m0 + m1;
                    }
                }
            }

            // masks are -1 => cnt is negative count
            #pragma unroll
            for (int f = 0; f < 30; f++)
                cnt[f] = __reduce_add_sync(0xffffffffu, cnt[f]);

            if (lane == 0) {
                int* dst = g_partial + ((i * 64 + n) * NKER + j) * 32;
                #pragma unroll
                for (int f = 0; f < 30; f++)
                    if (f < nf) atomicAdd(dst + f, -cnt[f]);
            }
        }
        g += seglen;
    }
}

// ---------------------------------------------------------------------------
// scale counts into output; re-zero partials so every graph replay is identical
__global__ void mr_fin(float* __restrict__ out)
{
    int t = blockIdx.x * 256 + threadIdx.x;
    if (t >= 4 * 64 * NKER * 30) return;
    int f = t % 30;
    int r = t / 30;
    int j = r % NKER; r /= NKER;
    int n = r % 64;
    int i = r / 64;
    int idx = ((i * 64 + n) * NKER + j) * 32 + f;
    int c = g_partial[idx];
    g_partial[idx] = 0;
    int nf = (i == 3) ? 29 : 30;
    if (f >= nf) return;
    float inv = (((i + j) & 1) == 0)
              ? (1.0f / 1024.0f)
              : (1.0f / (1024.0f - 8.0f * (float)(1 << i)));
    out[n * TOTF + i * 2520 + j * nf + f] = (float)c * inv;
}

// ---------------------------------------------------------------------------
extern "C" void kernel_launch(void* const* d_in, const int* in_sizes, int n_in,
                              void* d_out, int out_size)
{
    const float* x  = (const float*)d_in[0];
    const float* b  = (const float*)d_in[1];
    const int*   ci = (const int*)d_in[2];
    float* out = (float*)d_out;

    mr_main<<<592, 128>>>(x, b, ci);
    mr_fin<<<(4 * 64 * NKER * 30 + 255) / 256, 256>>>(out);
}

// round 8
// speedup vs baseline: 1.2198x; 1.2198x over previous
#include <cuda_runtime.h>
#include <math_constants.h>

// MiniRocket round 7 (resubmit — infra failure, identical source):
// strip-mined direct-compare, no atomics, no re-zero.
//  - 576 blocks = one wave: i=0 -> 64 samples x 3 thirds; i>=1 -> 64 x 2 halves.
//  - inner loop: phase 1 computes 4 csums/lane (128 positions/warp-strip),
//    phase 2 compares vs 30 biases (FSET mask + IADD3), registers only.
//  - partial counts -> fixed slots (plain STG.128), tiny div-free finalize.

#define NCH    8
#define LEN    1024
#define NKER   84
#define HALO   32
#define PITCHX 592            // max seglen 512 + 2*HALO + pad
#define PITCHS 528
#define TOTF   9996

// [i][n][slot(3)][j][32] partial counts (negative); every read slot is
// rewritten each launch (slot2 only exists for i=0, fin reads it only there).
__device__ __align__(16) int g_part[4 * 64 * 3 * NKER * 32];

__device__ __forceinline__ int fset_gt(float a, float b)
{
    int m;   // 0xFFFFFFFF if a > b else 0
    asm("set.gt.s32.f32 %0, %1, %2;" : "=r"(m) : "f"(a), "f"(b));
    return m;
}

// ---------------------------------------------------------------------------
__global__ __launch_bounds__(128, 4)
void mr_main(const float* __restrict__ x,
             const float* __restrict__ biases,
             const int* __restrict__ ci)
{
    __shared__ __align__(16) float Xq[NCH * PITCHX];
    __shared__ __align__(16) float Sq[NCH * PITCHS];
    __shared__ float bsh[NKER * 30];
    __shared__ int comb[NKER];

    const int tid = threadIdx.x, warp = tid >> 5, lane = tid & 31;

    // block -> (dilation i, sample n, segment [ls, ls+seglen), slot)
    int bid = blockIdx.x;
    int i, n, ls, seglen, slot;
    if (bid < 192) {                       // i = 0: thirds (scalar path)
        i = 0; n = bid / 3; slot = bid - n * 3;
        ls = slot * 342;
        seglen = (slot == 2) ? 340 : 342;
    } else {                               // i >= 1: halves (vector path)
        int r = bid - 192;
        i = 1 + (r >> 7);
        int rr = r & 127;
        n = rr >> 1; slot = rr & 1;
        ls = slot * 512; seglen = 512;
    }
    const int d = 1 << i, p = 4 * d;
    const int nf = (i == 3) ? 29 : 30;

    if (tid < NKER) {                      // 84 lexicographic triples of 0..8
        int t = 0, val = 0;
        for (int a = 0; a < 9; a++)
            for (int b2 = a + 1; b2 < 9; b2++)
                for (int c2 = b2 + 1; c2 < 9; c2++) {
                    if (t == tid) val = a | (b2 << 8) | (c2 << 16);
                    t++;
                }
        comb[tid] = val;
    }
    for (int k = tid; k < NKER * nf; k += 128)
        bsh[k] = biases[i * 2520 + k];

    // stage padded segment of x[n]
    for (int c = 0; c < NCH; c++) {
        const float* xc = x + (n * NCH + c) * LEN;
        for (int u = tid; u < seglen + 2 * HALO; u += 128) {
            int l = ls - HALO + u;
            Xq[c * PITCHX + u] = (l >= 0 && l < LEN) ? xc[l] : 0.0f;
        }
    }
    __syncthreads();
    // per-channel 9-tap dilated sums
    for (int c = 0; c < NCH; c++) {
        const float* xb = Xq + c * PITCHX + HALO;
        float* sc = Sq + c * PITCHS;
        for (int u = tid; u < seglen; u += 128) {
            float s = ((xb[u-4*d] + xb[u-3*d]) + (xb[u-2*d] + xb[u-d]))
                    + ((xb[u] + xb[u+d]) + (xb[u+2*d] + xb[u+3*d])) + xb[u+4*d];
            sc[u] = s;
        }
    }
    __syncthreads();

    const int nstrip = (seglen + 127) >> 7;   // 128-position strips

    for (int jj = 0; jj < 21; jj++) {         // each warp owns 21 kernels
        const int j = warp * 21 + jj;
        const int cm = comb[j];
        const int da = (((cm      ) & 255) - 4) * d;
        const int db = (((cm >>  8) & 255) - 4) * d;
        const int dc = (((cm >> 16) & 255) - 4) * d;
        const int* cp = ci + (i * NKER + j) * 3;
        const int c0 = cp[0], c1 = cp[1], c2 = cp[2];
        const float* X0 = Xq + c0 * PITCHX + HALO;
        const float* X1 = Xq + c1 * PITCHX + HALO;
        const float* X2 = Xq + c2 * PITCHX + HALO;
        const float* S0 = Sq + c0 * PITCHS;
        const float* S1 = Sq + c1 * PITCHS;
        const float* S2 = Sq + c2 * PITCHS;

        int vlo = 0, vhi = seglen;
        if ((i + j) & 1) {                    // odd parity: interior [p, L-p)
            vlo = max(0, p - ls);
            vhi = min(seglen, LEN - p - ls);
        }
        const unsigned lim = (unsigned)max(0, vhi - vlo);  // clamp (R4 bug)

        float bv[30];
        int   cnt[30];
        const float* bp = bsh + j * nf;
        #pragma unroll
        for (int f = 0; f < 30; f++) {
            bv[f]  = (f < nf) ? bp[f] : CUDART_INF_F;
            cnt[f] = 0;
        }

        for (int st = 0; st < nstrip; st++) {
            const int base = st << 7;
            float cs[4];
            if (i == 0) {                     // scalar (odd tap offsets)
                #pragma unroll
                for (int k = 0; k < 4; k++) {
                    const int u = base + lane + 32 * k;
                    float a = ((X0[u+da] + X0[u+db]) + (X0[u+dc] + X1[u+da]))
                            + ((X1[u+db] + X1[u+dc]) + (X2[u+da] + X2[u+db]))
                            + X2[u+dc];
                    float c = fmaf(3.0f, a, -(S0[u] + S1[u] + S2[u]));
                    if ((unsigned)(u - vlo) >= lim) c = -CUDART_INF_F;
                    cs[k] = c;
                }
            } else {                          // float2 (even offsets, aligned)
                #pragma unroll
                for (int k = 0; k < 2; k++) {
                    const int u0 = base + 2 * lane + 64 * k;
                    float2 a0 = *(const float2*)(X0 + u0 + da);
                    float2 a1 = *(const float2*)(X0 + u0 + db);
                    float2 a2 = *(const float2*)(X0 + u0 + dc);
                    float2 a3 = *(const float2*)(X1 + u0 + da);
                    float2 a4 = *(const float2*)(X1 + u0 + db);
                    float2 a5 = *(const float2*)(X1 + u0 + dc);
                    float2 a6 = *(const float2*)(X2 + u0 + da);
                    float2 a7 = *(const float2*)(X2 + u0 + db);
                    float2 a8 = *(const float2*)(X2 + u0 + dc);
                    float2 s0 = *(const float2*)(S0 + u0);
                    float2 s1 = *(const float2*)(S1 + u0);
                    float2 s2 = *(const float2*)(S2 + u0);
                    float ax = ((a0.x+a1.x)+(a2.x+a3.x)) + ((a4.x+a5.x)+(a6.x+a7.x)) + a8.x;
                    float ay = ((a0.y+a1.y)+(a2.y+a3.y)) + ((a4.y+a5.y)+(a6.y+a7.y)) + a8.y;
                    float cx = fmaf(3.0f, ax, -(s0.x + s1.x + s2.x));
                    float cy = fmaf(3.0f, ay, -(s0.y + s1.y + s2.y));
                    const unsigned q0 = (unsigned)(u0 - vlo);
                    if (q0 >= lim)      cx = -CUDART_INF_F;
                    if (q0 + 1u >= lim) cy = -CUDART_INF_F;
                    cs[2*k]   = cx;
                    cs[2*k+1] = cy;
                }
            }
            // compare phase: register-only, 6 instrs per feature per 4 pos
            #pragma unroll
            for (int f = 0; f < 30; f++) {
                int m0 = fset_gt(cs[0], bv[f]);
                int m1 = fset_gt(cs[1], bv[f]);
                int m2 = fset_gt(cs[2], bv[f]);
                int m3 = fset_gt(cs[3], bv[f]);
                cnt[f] += m0 + m1;
                cnt[f] += m2 + m3;
            }
        }

        #pragma unroll
        for (int f = 0; f < 30; f++)
            cnt[f] = __reduce_add_sync(0xffffffffu, cnt[f]);

        if (lane == 0) {                      // plain stores to fixed slot
            int* dst = g_part + (((i * 64 + n) * 3 + slot) * NKER + j) * 32;
            #pragma unroll
            for (int w = 0; w < 7; w++)
                *reinterpret_cast<int4*>(dst + w * 4) =
                    make_int4(cnt[w*4], cnt[w*4+1], cnt[w*4+2], cnt[w*4+3]);
            dst[28] = cnt[28];
            dst[29] = cnt[29];
        }
    }
}

// ---------------------------------------------------------------------------
// sum fixed slots, scale, scatter; no divides, no writes back to g_part.
__global__ void mr_fin(float* __restrict__ out)
{
    const int j = blockIdx.x;                 // 84
    const int i = blockIdx.y;                 // 4
    const int n = blockIdx.z * 8 + threadIdx.y;
    const int f = threadIdx.x;                // 30
    const int nf = (i == 3) ? 29 : 30;
    if (f >= nf) return;

    const int base = (((i * 64 + n) * 3) * NKER + j) * 32 + f;
    const int ss   = NKER * 32;               // slot stride
    int c = g_part[base] + g_part[base + ss];
    if (i == 0) c += g_part[base + 2 * ss];   // thirds

    const float inv = (((i + j) & 1) == 0)
                    ? (1.0f / 1024.0f)
                    : (1.0f / (1024.0f - 8.0f * (float)(1 << i)));
    out[n * TOTF + i * 2520 + j * nf + f] = (float)(-c) * inv;
}

// ---------------------------------------------------------------------------
extern "C" void kernel_launch(void* const* d_in, const int* in_sizes, int n_in,
                              void* d_out, int out_size)
{
    const float* x  = (const float*)d_in[0];
    const float* b  = (const float*)d_in[1];
    const int*   ci = (const int*)d_in[2];
    float* out = (float*)d_out;

    // allow 4 x 46KB blocks of static smem to co-reside
    cudaFuncSetAttribute(mr_main,
                         cudaFuncAttributePreferredSharedMemoryCarveout, 100);

    mr_main<<<576, 128>>>(x, b, ci);
    mr_fin<<<dim3(NKER, 4, 8), dim3(30, 8)>>>(out);
}

// round 9
// speedup vs baseline: 1.2606x; 1.0335x over previous
#include <cuda_runtime.h>
#include <math_constants.h>

// MiniRocket round 9: round-8 structure + pipe-balanced compares.
// 15 features compared as floats (fma pipe), 15 as order-preserving uint
// keys (alu pipe: ISETP/IADD). key(x) = bits ^ ((bits>>31)|0x80000000) is
// exactly order-isomorphic to float compare for non-NaN values.

#define NCH    8
#define LEN    1024
#define NKER   84
#define HALO   32
#define PITCHX 592
#define PITCHS 528
#define TOTF   9996

// [i][n][slot(3)][j][32] partial counts (negative); every read slot is
// rewritten each launch (slot2 only exists for i=0, fin reads it only there).
__device__ __align__(16) int g_part[4 * 64 * 3 * NKER * 32];

__device__ __forceinline__ int fset_gt(float a, float b)
{
    int m;   // 0xFFFFFFFF if a > b else 0
    asm("set.gt.s32.f32 %0, %1, %2;" : "=r"(m) : "f"(a), "f"(b));
    return m;
}

// order-preserving float -> uint key (monotone; -inf lowest, +inf highest)
__device__ __forceinline__ unsigned fkey(float x)
{
    int b = __float_as_int(x);
    return (unsigned)(b ^ ((b >> 31) | 0x80000000));
}

// ---------------------------------------------------------------------------
__global__ __launch_bounds__(128, 4)
void mr_main(const float* __restrict__ x,
             const float* __restrict__ biases,
             const int* __restrict__ ci)
{
    __shared__ __align__(16) float Xq[NCH * PITCHX];
    __shared__ __align__(16) float Sq[NCH * PITCHS];
    __shared__ float bsh[NKER * 30];
    __shared__ int comb[NKER];

    const int tid = threadIdx.x, warp = tid >> 5, lane = tid & 31;

    // block -> (dilation i, sample n, segment [ls, ls+seglen), slot)
    int bid = blockIdx.x;
    int i, n, ls, seglen, slot;
    if (bid < 192) {                       // i = 0: thirds (scalar path)
        i = 0; n = bid / 3; slot = bid - n * 3;
        ls = slot * 342;
        seglen = (slot == 2) ? 340 : 342;
    } else {                               // i >= 1: halves (vector path)
        int r = bid - 192;
        i = 1 + (r >> 7);
        int rr = r & 127;
        n = rr >> 1; slot = rr & 1;
        ls = slot * 512; seglen = 512;
    }
    const int d = 1 << i, p = 4 * d;
    const int nf = (i == 3) ? 29 : 30;

    if (tid < NKER) {                      // 84 lexicographic triples of 0..8
        int t = 0, val = 0;
        for (int a = 0; a < 9; a++)
            for (int b2 = a + 1; b2 < 9; b2++)
                for (int c2 = b2 + 1; c2 < 9; c2++) {
                    if (t == tid) val = a | (b2 << 8) | (c2 << 16);
                    t++;
                }
        comb[tid] = val;
    }
    for (int k = tid; k < NKER * nf; k += 128)
        bsh[k] = biases[i * 2520 + k];

    // stage padded segment of x[n]
    for (int c = 0; c < NCH; c++) {
        const float* xc = x + (n * NCH + c) * LEN;
        for (int u = tid; u < seglen + 2 * HALO; u += 128) {
            int l = ls - HALO + u;
            Xq[c * PITCHX + u] = (l >= 0 && l < LEN) ? xc[l] : 0.0f;
        }
    }
    __syncthreads();
    // per-channel 9-tap dilated sums
    for (int c = 0; c < NCH; c++) {
        const float* xb = Xq + c * PITCHX + HALO;
        float* sc = Sq + c * PITCHS;
        for (int u = tid; u < seglen; u += 128) {
            float s = ((xb[u-4*d] + xb[u-3*d]) + (xb[u-2*d] + xb[u-d]))
                    + ((xb[u] + xb[u+d]) + (xb[u+2*d] + xb[u+3*d])) + xb[u+4*d];
            sc[u] = s;
        }
    }
    __syncthreads();

    const int nstrip = (seglen + 127) >> 7;   // 128-position strips

    for (int jj = 0; jj < 21; jj++) {         // each warp owns 21 kernels
        const int j = warp * 21 + jj;
        const int cm = comb[j];
        const int da = (((cm      ) & 255) - 4) * d;
        const int db = (((cm >>  8) & 255) - 4) * d;
        const int dc = (((cm >> 16) & 255) - 4) * d;
        const int* cp = ci + (i * NKER + j) * 3;
        const int c0 = cp[0], c1 = cp[1], c2 = cp[2];
        const float* X0 = Xq + c0 * PITCHX + HALO;
        const float* X1 = Xq + c1 * PITCHX + HALO;
        const float* X2 = Xq + c2 * PITCHX + HALO;
        const float* S0 = Sq + c0 * PITCHS;
        const float* S1 = Sq + c1 * PITCHS;
        const float* S2 = Sq + c2 * PITCHS;

        int vlo = 0, vhi = seglen;
        if ((i + j) & 1) {                    // odd parity: interior [p, L-p)
            vlo = max(0, p - ls);
            vhi = min(seglen, LEN - p - ls);
        }
        const unsigned lim = (unsigned)max(0, vhi - vlo);  // clamp (R4 bug)

        // features 0..14 -> float compares (fma pipe)
        // features 15..29 -> uint-key compares (alu pipe)
        float    bvf[15];
        unsigned kbv[15];
        int      cf[15], cn[15];
        const float* bp = bsh + j * nf;
        #pragma unroll
        for (int f = 0; f < 15; f++) {
            bvf[f] = (f < nf) ? bp[f] : CUDART_INF_F;
            float bi = (f + 15 < nf) ? bp[f + 15] : CUDART_INF_F;
            kbv[f] = fkey(bi);
            cf[f] = 0; cn[f] = 0;
        }

        for (int st = 0; st < nstrip; st++) {
            const int base = st << 7;
            float cs[4];
            if (i == 0) {                     // scalar (odd tap offsets)
                #pragma unroll
                for (int k = 0; k < 4; k++) {
                    const int u = base + lane + 32 * k;
                    float a = ((X0[u+da] + X0[u+db]) + (X0[u+dc] + X1[u+da]))
                            + ((X1[u+db] + X1[u+dc]) + (X2[u+da] + X2[u+db]))
                            + X2[u+dc];
                    float c = fmaf(3.0f, a, -(S0[u] + S1[u] + S2[u]));
                    if ((unsigned)(u - vlo) >= lim) c = -CUDART_INF_F;
                    cs[k] = c;
                }
            } else {                          // float2 (even offsets, aligned)
                #pragma unroll
                for (int k = 0; k < 2; k++) {
                    const int u0 = base + 2 * lane + 64 * k;
                    float2 a0 = *(const float2*)(X0 + u0 + da);
                    float2 a1 = *(const float2*)(X0 + u0 + db);
                    float2 a2 = *(const float2*)(X0 + u0 + dc);
                    float2 a3 = *(const float2*)(X1 + u0 + da);
                    float2 a4 = *(const float2*)(X1 + u0 + db);
                    float2 a5 = *(const float2*)(X1 + u0 + dc);
                    float2 a6 = *(const float2*)(X2 + u0 + da);
                    float2 a7 = *(const float2*)(X2 + u0 + db);
                    float2 a8 = *(const float2*)(X2 + u0 + dc);
                    float2 s0 = *(const float2*)(S0 + u0);
                    float2 s1 = *(const float2*)(S1 + u0);
                    float2 s2 = *(const float2*)(S2 + u0);
                    float ax = ((a0.x+a1.x)+(a2.x+a3.x)) + ((a4.x+a5.x)+(a6.x+a7.x)) + a8.x;
                    float ay = ((a0.y+a1.y)+(a2.y+a3.y)) + ((a4.y+a5.y)+(a6.y+a7.y)) + a8.y;
                    float cx = fmaf(3.0f, ax, -(s0.x + s1.x + s2.x));
                    float cy = fmaf(3.0f, ay, -(s0.y + s1.y + s2.y));
                    const unsigned q0 = (unsigned)(u0 - vlo);
                    if (q0 >= lim)      cx = -CUDART_INF_F;
                    if (q0 + 1u >= lim) cy = -CUDART_INF_F;
                    cs[2*k]   = cx;
                    cs[2*k+1] = cy;
                }
            }
            const unsigned k0 = fkey(cs[0]), k1 = fkey(cs[1]);
            const unsigned k2 = fkey(cs[2]), k3 = fkey(cs[3]);
            // register-only compare phase, split across fma and alu pipes
            #pragma unroll
            for (int f = 0; f < 15; f++) {
                cf[f] += fset_gt(cs[0], bvf[f]) + fset_gt(cs[1], bvf[f]);
                cf[f] += fset_gt(cs[2], bvf[f]) + fset_gt(cs[3], bvf[f]);
                cn[f] += (int)(k0 > kbv[f]) + (int)(k1 > kbv[f]);
                cn[f] += (int)(k2 > kbv[f]) + (int)(k3 > kbv[f]);
            }
        }

        #pragma unroll
        for (int f = 0; f < 15; f++) {
            cf[f] = __reduce_add_sync(0xffffffffu, cf[f]);   // negative
            cn[f] = __reduce_add_sync(0xffffffffu, cn[f]);   // positive
        }

        if (lane == 0) {                      // plain stores to fixed slot
            int out30[30];
            #pragma unroll
            for (int f = 0; f < 15; f++) {
                out30[f]      = cf[f];        // already negative
                out30[f + 15] = -cn[f];       // store negative
            }
            int* dst = g_part + (((i * 64 + n) * 3 + slot) * NKER + j) * 32;
            #pragma unroll
            for (int w = 0; w < 7; w++)
                *reinterpret_cast<int4*>(dst + w * 4) =
                    make_int4(out30[w*4], out30[w*4+1], out30[w*4+2], out30[w*4+3]);
            dst[28] = out30[28];
            dst[29] = out30[29];
        }
    }
}

// ---------------------------------------------------------------------------
// sum fixed slots, scale, scatter; no divides, no writes back to g_part.
__global__ void mr_fin(float* __restrict__ out)
{
    const int j = blockIdx.x;                 // 84
    const int i = blockIdx.y;                 // 4
    const int n = blockIdx.z * 8 + threadIdx.y;
    const int f = threadIdx.x;                // 30
    const int nf = (i == 3) ? 29 : 30;
    if (f >= nf) return;

    const int base = (((i * 64 + n) * 3) * NKER + j) * 32 + f;
    const int ss   = NKER * 32;               // slot stride
    int c = g_part[base] + g_part[base + ss];
    if (i == 0) c += g_part[base + 2 * ss];   // thirds

    const float inv = (((i + j) & 1) == 0)
                    ? (1.0f / 1024.0f)
                    : (1.0f / (1024.0f - 8.0f * (float)(1 << i)));
    out[n * TOTF + i * 2520 + j * nf + f] = (float)(-c) * inv;
}

// ---------------------------------------------------------------------------
extern "C" void kernel_launch(void* const* d_in, const int* in_sizes, int n_in,
                              void* d_out, int out_size)
{
    const float* x  = (const float*)d_in[0];
    const float* b  = (const float*)d_in[1];
    const int*   ci = (const int*)d_in[2];
    float* out = (float*)d_out;

    cudaFuncSetAttribute(mr_main,
                         cudaFuncAttributePreferredSharedMemoryCarveout, 100);

    mr_main<<<576, 128>>>(x, b, ci);
    mr_fin<<<dim3(NKER, 4, 8), dim3(30, 8)>>>(out);
}